// round 11
// baseline (speedup 1.0000x reference)
#include <cuda_runtime.h>
#include <cuda_bf16.h>

#define BATCH 256

// zero-value basis constants: v=0 -> t=4.5, i0=4, u=0.5
#define ZB2 (1.f/48.f)
#define ZB3 (23.f/48.f)

typedef unsigned long long u64;

// ---------------- packed f32x2 helpers (Blackwell FFMA2) -------------------
__device__ __forceinline__ u64 pack_dup(float x) {
    u64 r; asm("mov.b64 %0, {%1, %1};" : "=l"(r) : "f"(x)); return r;
}
__device__ __forceinline__ void unpack2(u64 v, float& x, float& y) {
    asm("mov.b64 {%0, %1}, %2;" : "=f"(x), "=f"(y) : "l"(v));
}
__device__ __forceinline__ void ffma2(u64& d, u64 a, u64 b) {
    asm("fma.rn.f32x2 %0, %1, %2, %0;" : "+l"(d) : "l"(a), "l"(b));
}

// ---------------- scratch (static device globals) ---------------------------
// SoA basis: [B][C][7 slots][P rows][RP padded cols]
__device__ float d_bas1 [BATCH * 3  * 7 * 34 * 36];
__device__ float d_bas2 [BATCH * 8  * 7 * 18 * 20];
__device__ float d_bas3 [BATCH * 16 * 7 * 10 * 12];
__device__ float d_pool3[BATCH * 32 * 4 * 4];
// weights: L1 [27][7][8]; L2 [4 tiles][72][7][4]; L3 [144][7][32]
__device__ float d_sw1[27  * 7 * 8];
__device__ float d_sw2[4 * 72 * 7 * 4];
__device__ float d_sw3[144 * 7 * 32];
__device__ float d_wt [512 * 100];   // transposed lin_w: [k][o]

// ---------------- basis evaluation (7 slots) --------------------------------
__device__ __forceinline__ void basis7(float v, float* sv) {
    sv[0] = v * (1.f / (1.f + __expf(-v)));          // silu
    float t  = (v + 3.f) * 1.5f;
    bool valid = (t >= 0.f) && (t < 9.f);
    float fi = floorf(t);
    int   i0 = (int)fi;
    float u  = t - fi;
    float u2 = u * u, u3 = u2 * u;
    float q3 = u3 * (1.f / 6.f);
    float q2 = ((3.f * u2 - 3.f * u3) + 3.f * u + 1.f) * (1.f / 6.f);
    float q1 = (3.f * u3 - 6.f * u2 + 4.f) * (1.f / 6.f);
    float iu = 1.f - u;
    float q0 = iu * iu * iu * (1.f / 6.f);
    if (!valid) { q0 = q1 = q2 = q3 = 0.f; i0 = -1000; }
#pragma unroll
    for (int m = 0; m < 6; m++) {
        int d = i0 - m;
        sv[1 + m] = (d == 0) ? q3 : (d == 1) ? q2 : (d == 2) ? q1
                  : (d == 3) ? q0 : 0.f;
    }
}

// ---------------- layer-1 input basis (SoA) ---------------------------------
__global__ void basis_in_kernel(const float* __restrict__ X, float* __restrict__ BAS) {
    constexpr int P = 34, RP = 36, HW = 32;
    int idx = blockIdx.x * blockDim.x + threadIdx.x;
    if (idx >= BATCH * 3 * P * P) return;
    int xp = idx % P;
    int yp = (idx / P) % P;
    int bc = idx / (P * P);
    float sv[7];
    if (xp == 0 || xp == P - 1 || yp == 0 || yp == P - 1) {
        sv[0] = 0.f; sv[1] = 0.f; sv[2] = ZB2; sv[3] = ZB3;
        sv[4] = ZB3; sv[5] = ZB2; sv[6] = 0.f;
    } else {
        float v = X[((long)bc * HW + (yp - 1)) * HW + (xp - 1)];
        basis7(v, sv);
    }
    float* base = BAS + ((long)bc * 7 * P + yp) * RP + xp;
#pragma unroll
    for (int s = 0; s < 7; s++) base[(long)s * P * RP] = sv[s];
}

// -------- layer-1: smem-staged conv3x3 + pool + bas2 write ------------------
// block = half image (16 conv rows), 128 threads = 16 rows x 4 x-groups(POS=4)
// wait: 16 rows x 8 x-groups = 128. All 8 output channels per thread.
__global__ void __launch_bounds__(128)
convpool1_kernel(const float* __restrict__ BAS,   // [B][3][7][34][36]
                 const float* __restrict__ SW,    // [27][7][8]
                 float* __restrict__ OUT) {       // bas2 [B][8][7][18][20]
    constexpr int P = 34, RP = 36;
    __shared__ __align__(16) float sw[27 * 7 * 8];        // 6048 B
    __shared__ __align__(16) float sb[7 * 18 * RP];       // 18144 B

    int tid = threadIdx.x;
    int b   = blockIdx.x >> 1;
    int y0  = (blockIdx.x & 1) * 16;
    int k   = tid & 7;           // x-group, x0 = 4k
    int yl  = tid >> 3;          // 0..15
    int x0  = 4 * k;

    for (int i = tid; i < 27 * 7 * 8 / 4; i += 128)
        reinterpret_cast<float4*>(sw)[i] = reinterpret_cast<const float4*>(SW)[i];

    u64 acc2[4][4];              // [pos][channel pair]
#pragma unroll
    for (int pos = 0; pos < 4; pos++)
#pragma unroll
        for (int q = 0; q < 4; q++) acc2[pos][q] = 0ull;

    for (int c = 0; c < 3; c++) {
        __syncthreads();
        const float* src = BAS + ((long)(b * 3 + c) * 7 * P + y0) * RP;
        for (int i = tid; i < 7 * 162; i += 128) {        // 18*36/4 = 162 f4 per slot
            int s = i / 162, r = i % 162;
            reinterpret_cast<float4*>(sb)[s * 162 + r] =
                reinterpret_cast<const float4*>(src + (long)s * P * RP)[r];
        }
        __syncthreads();
#pragma unroll
        for (int ky = 0; ky < 3; ky++) {
            float bv[7][6];
#pragma unroll
            for (int s = 0; s < 7; s++) {
                const float* q = sb + (s * 18 + (yl + ky)) * RP + x0;
                float4 a = *reinterpret_cast<const float4*>(q);
                float2 e = *reinterpret_cast<const float2*>(q + 4);
                bv[s][0] = a.x; bv[s][1] = a.y; bv[s][2] = a.z;
                bv[s][3] = a.w; bv[s][4] = e.x; bv[s][5] = e.y;
            }
#pragma unroll
            for (int kx = 0; kx < 3; kx++) {
#pragma unroll
                for (int s = 0; s < 7; s++) {
                    const float* wp = sw + ((c * 9 + ky * 3 + kx) * 7 + s) * 8;
                    ulonglong2 wA = *reinterpret_cast<const ulonglong2*>(wp);
                    ulonglong2 wB = *reinterpret_cast<const ulonglong2*>(wp + 4);
#pragma unroll
                    for (int pos = 0; pos < 4; pos++) {
                        u64 sp = pack_dup(bv[s][kx + pos]);
                        ffma2(acc2[pos][0], sp, wA.x);
                        ffma2(acc2[pos][1], sp, wA.y);
                        ffma2(acc2[pos][2], sp, wB.x);
                        ffma2(acc2[pos][3], sp, wB.y);
                    }
                }
            }
        }
    }

    // pool: horizontal within thread, vertical via shfl (partner yl^1 = lane^8)
    float hm[2][8];
#pragma unroll
    for (int q = 0; q < 4; q++)
#pragma unroll
        for (int xl = 0; xl < 2; xl++) {
            float a0, a1, b0, b1;
            unpack2(acc2[2 * xl][q],     a0, a1);
            unpack2(acc2[2 * xl + 1][q], b0, b1);
            hm[xl][2 * q]     = fmaxf(a0, b0);
            hm[xl][2 * q + 1] = fmaxf(a1, b1);
        }
#pragma unroll
    for (int xl = 0; xl < 2; xl++)
#pragma unroll
        for (int j = 0; j < 8; j++) {
            float o = __shfl_xor_sync(0xffffffffu, hm[xl][j], 8);
            hm[xl][j] = fmaxf(hm[xl][j], o);
        }

    if ((yl & 1) == 0) {
        int yo = (y0 + yl) >> 1;
#pragma unroll
        for (int j = 0; j < 8; j++)
#pragma unroll
            for (int xl = 0; xl < 2; xl++) {
                float sv[7];
                basis7(hm[xl][j], sv);
                float* base = OUT + (((long)(b * 8 + j) * 7) * 18 + (yo + 1)) * 20
                                  + (2 * k + xl + 1);
#pragma unroll
                for (int s = 0; s < 7; s++) base[(long)s * 18 * 20] = sv[s];
            }
    }
}

// -------- layer-2: smem-staged conv3x3 + pool + bas3 write ------------------
// block = half image (8 conv rows) x all 16 out channels; 128 threads:
// warp = channel tile (4 ch), lane = yl*4 + k (yl 0..7, x0 = 4k).
__global__ void __launch_bounds__(128)
convpool2_kernel(const float* __restrict__ BAS,   // [B][8][7][18][20]
                 const float* __restrict__ SW,    // [4][72][7][4]
                 float* __restrict__ OUT) {       // bas3 [B][16][7][10][12]
    __shared__ __align__(16) float sw[4 * 72 * 7 * 4];    // 32256 B
    __shared__ __align__(16) float sb[7 * 10 * 20];       // 5600 B

    int tid  = threadIdx.x;
    int b    = blockIdx.x >> 1;
    int y0   = (blockIdx.x & 1) * 8;
    int tile = tid >> 5;
    int lane = tid & 31;
    int k    = lane & 3;
    int yl   = lane >> 2;
    int x0   = 4 * k;

    for (int i = tid; i < 4 * 72 * 7 * 4 / 4; i += 128)
        reinterpret_cast<float4*>(sw)[i] = reinterpret_cast<const float4*>(SW)[i];

    u64 acc2[4][2];
#pragma unroll
    for (int pos = 0; pos < 4; pos++) { acc2[pos][0] = 0ull; acc2[pos][1] = 0ull; }

    for (int c = 0; c < 8; c++) {
        __syncthreads();
        const float* src = BAS + ((long)(b * 8 + c) * 7 * 18 + y0) * 20;
        for (int i = tid; i < 7 * 50; i += 128) {         // 10*20/4 = 50 f4 per slot
            int s = i / 50, r = i % 50;
            reinterpret_cast<float4*>(sb)[s * 50 + r] =
                reinterpret_cast<const float4*>(src + (long)s * 18 * 20)[r];
        }
        __syncthreads();
#pragma unroll
        for (int ky = 0; ky < 3; ky++) {
            float bv[7][6];
#pragma unroll
            for (int s = 0; s < 7; s++) {
                const float* q = sb + (s * 10 + (yl + ky)) * 20 + x0;
                float4 a = *reinterpret_cast<const float4*>(q);
                float2 e = *reinterpret_cast<const float2*>(q + 4);
                bv[s][0] = a.x; bv[s][1] = a.y; bv[s][2] = a.z;
                bv[s][3] = a.w; bv[s][4] = e.x; bv[s][5] = e.y;
            }
#pragma unroll
            for (int kx = 0; kx < 3; kx++) {
#pragma unroll
                for (int s = 0; s < 7; s++) {
                    const float* wp = sw + (((tile * 72 + (c * 9 + ky * 3 + kx)) * 7 + s)) * 4;
                    ulonglong2 w = *reinterpret_cast<const ulonglong2*>(wp);
#pragma unroll
                    for (int pos = 0; pos < 4; pos++) {
                        u64 sp = pack_dup(bv[s][kx + pos]);
                        ffma2(acc2[pos][0], sp, w.x);
                        ffma2(acc2[pos][1], sp, w.y);
                    }
                }
            }
        }
    }

    // pool: horizontal, then vertical via shfl (partner yl^1 = lane^4)
    float hm[2][4];
#pragma unroll
    for (int q = 0; q < 2; q++)
#pragma unroll
        for (int xl = 0; xl < 2; xl++) {
            float a0, a1, b0, b1;
            unpack2(acc2[2 * xl][q],     a0, a1);
            unpack2(acc2[2 * xl + 1][q], b0, b1);
            hm[xl][2 * q]     = fmaxf(a0, b0);
            hm[xl][2 * q + 1] = fmaxf(a1, b1);
        }
#pragma unroll
    for (int xl = 0; xl < 2; xl++)
#pragma unroll
        for (int j = 0; j < 4; j++) {
            float o = __shfl_xor_sync(0xffffffffu, hm[xl][j], 4);
            hm[xl][j] = fmaxf(hm[xl][j], o);
        }

    if ((yl & 1) == 0) {
        int yo = (y0 + yl) >> 1;
#pragma unroll
        for (int j = 0; j < 4; j++)
#pragma unroll
            for (int xl = 0; xl < 2; xl++) {
                float sv[7];
                basis7(hm[xl][j], sv);
                int ch = tile * 4 + j;
                float* base = OUT + (((long)(b * 16 + ch) * 7) * 10 + (yo + 1)) * 12
                                  + (2 * k + xl + 1);
#pragma unroll
                for (int s = 0; s < 7; s++) base[(long)s * 10 * 12] = sv[s];
            }
    }
}

// -------- layer-3: smem-staged conv + pool (all 32 channels per block) ------
__global__ void __launch_bounds__(64)
convpool3_kernel(const float* __restrict__ BAS,   // [B][16][7][10][12]
                 const float* __restrict__ SW,    // [144][7][32]
                 float* __restrict__ OUTP) {      // [B][32][4][4]
    constexpr int P = 10, RP = 12, ROWS = 6;
    __shared__ __align__(16) float tile[8 * 7 * ROWS * RP];   // 16128 B

    int tid = threadIdx.x;
    int r   = tid & 3;
    int tl  = tid >> 2;
    int b   = blockIdx.x >> 1;
    int y0  = (blockIdx.x & 1) * 4;

    u64 acc2[8];
#pragma unroll
    for (int pos = 0; pos < 8; pos++) acc2[pos] = 0ull;

    for (int ph = 0; ph < 2; ph++) {
        __syncthreads();
        for (int i = tid; i < 8 * 7 * 18; i += 64) {
            int cs = i / 18, rr = i % 18;
            const float4* src = reinterpret_cast<const float4*>(
                BAS + ((long)((b * 16 + ph * 8 + cs / 7) * 7 + cs % 7) * P + y0) * RP) + rr;
            reinterpret_cast<float4*>(tile)[cs * 18 + rr] = *src;
        }
        __syncthreads();

        for (int cl = 0; cl < 8; cl++) {
#pragma unroll
            for (int ky = 0; ky < 3; ky++) {
                float bv[7][10];
#pragma unroll
                for (int s = 0; s < 7; s++) {
                    const float* q = tile + ((cl * 7 + s) * ROWS + (r + ky)) * RP;
                    float4 a = *reinterpret_cast<const float4*>(q);
                    float4 d = *reinterpret_cast<const float4*>(q + 4);
                    float2 e = *reinterpret_cast<const float2*>(q + 8);
                    bv[s][0] = a.x; bv[s][1] = a.y; bv[s][2] = a.z; bv[s][3] = a.w;
                    bv[s][4] = d.x; bv[s][5] = d.y; bv[s][6] = d.z; bv[s][7] = d.w;
                    bv[s][8] = e.x; bv[s][9] = e.y;
                }
                const float* wb = SW + ((long)((ph * 8 + cl) * 9 + ky * 3) * 7) * 32 + tl * 2;
#pragma unroll
                for (int kx = 0; kx < 3; kx++) {
#pragma unroll
                    for (int s = 0; s < 7; s++) {
                        u64 w = *reinterpret_cast<const u64*>(wb + (kx * 7 + s) * 32);
#pragma unroll
                        for (int pos = 0; pos < 8; pos++) {
                            u64 sp = pack_dup(bv[s][kx + pos]);
                            ffma2(acc2[pos], sp, w);
                        }
                    }
                }
            }
        }
    }

    float hm[4][2];
#pragma unroll
    for (int xo = 0; xo < 4; xo++) {
        float a0, a1, b0, b1;
        unpack2(acc2[2 * xo],     a0, a1);
        unpack2(acc2[2 * xo + 1], b0, b1);
        hm[xo][0] = fmaxf(a0, b0);
        hm[xo][1] = fmaxf(a1, b1);
    }
#pragma unroll
    for (int xo = 0; xo < 4; xo++)
#pragma unroll
        for (int j = 0; j < 2; j++) {
            float o = __shfl_xor_sync(0xffffffffu, hm[xo][j], 1);
            hm[xo][j] = fmaxf(hm[xo][j], o);
        }

    if ((r & 1) == 0) {
        int yo = (y0 + r) >> 1;
#pragma unroll
        for (int j = 0; j < 2; j++) {
            int ch = tl * 2 + j;
            float4 v = make_float4(hm[0][j], hm[1][j], hm[2][j], hm[3][j]);
            *reinterpret_cast<float4*>(OUTP + (((long)b * 32 + ch) * 4 + yo) * 4) = v;
        }
    }
}

// ---------------- merged weight prep + SoA halo fill ------------------------
__device__ __forceinline__ float sw_val(const float* bw, const float* sp,
                                        const float* sc, int o, int f, int slot, int F) {
    if (slot == 0) return bw[o * F + f];
    return sp[(o * F + f) * 6 + (slot - 1)] * sc[o * F + f];
}

__device__ __forceinline__ void halo_fill(float* bas, int i, int P, int RP) {
    int hc  = 4 * P - 4;
    int img = i / hc;
    int kk  = i % hc;
    int xp, yp;
    if (kk < P)          { yp = 0;      xp = kk; }
    else if (kk < 2 * P) { yp = P - 1;  xp = kk - P; }
    else {
        int rr = kk - 2 * P;
        yp = 1 + (rr >> 1);
        xp = (rr & 1) ? (P - 1) : 0;
    }
    const float zb[7] = {0.f, 0.f, ZB2, ZB3, ZB3, ZB2, 0.f};
    float* base = bas + ((long)img * 7 * P + yp) * RP + xp;
#pragma unroll
    for (int s = 0; s < 7; s++) base[(long)s * P * RP] = zb[s];
}

__global__ void prep_all_kernel(const float* __restrict__ c1_bw, const float* __restrict__ c1_sw,
                                const float* __restrict__ c1_sc,
                                const float* __restrict__ c2_bw, const float* __restrict__ c2_sw,
                                const float* __restrict__ c2_sc,
                                const float* __restrict__ c3_bw, const float* __restrict__ c3_sw,
                                const float* __restrict__ c3_sc,
                                const float* __restrict__ lin_w,
                                float* __restrict__ sw1, float* __restrict__ sw2,
                                float* __restrict__ sw3, float* __restrict__ wt,
                                float* __restrict__ bas2, float* __restrict__ bas3) {
    const int N1 = 8 * 27 * 7, N2 = 16 * 72 * 7, N3 = 32 * 144 * 7, NW = 100 * 512;
    const int H2 = BATCH * 8 * (4 * 18 - 4);
    const int H3 = BATCH * 16 * (4 * 10 - 4);
    int idx = blockIdx.x * blockDim.x + threadIdx.x;
    int e1 = N1, e2 = e1 + N2, e3 = e2 + N3, e4 = e3 + NW, e5 = e4 + H2, e6 = e5 + H3;
    if (idx < e1) {
        int slot = idx % 7, f = (idx / 7) % 27, o = idx / (7 * 27);
        sw1[(f * 7 + slot) * 8 + o] = sw_val(c1_bw, c1_sw, c1_sc, o, f, slot, 27);
    } else if (idx < e2) {
        int i = idx - e1;
        int slot = i % 7, f = (i / 7) % 72, o = i / (7 * 72);
        sw2[(((o >> 2) * 72 + f) * 7 + slot) * 4 + (o & 3)] =
            sw_val(c2_bw, c2_sw, c2_sc, o, f, slot, 72);
    } else if (idx < e3) {
        int i = idx - e2;
        int slot = i % 7, f = (i / 7) % 144, o = i / (7 * 144);
        sw3[(f * 7 + slot) * 32 + o] = sw_val(c3_bw, c3_sw, c3_sc, o, f, slot, 144);
    } else if (idx < e4) {
        int i = idx - e3;
        int o = i / 512, k = i % 512;
        wt[k * 100 + o] = lin_w[i];
    } else if (idx < e5) halo_fill(bas2, idx - e4, 18, 20);
    else if (idx < e6)   halo_fill(bas3, idx - e5, 10, 12);
}

// ---------------- final linear: [256,512] @ [512,100]^T + b -----------------
__global__ void __launch_bounds__(128)
linear_kernel(const float* __restrict__ X, const float* __restrict__ WT,
              const float* __restrict__ bias, float* __restrict__ out) {
    __shared__ float xs[4][512];
    int b0 = blockIdx.x * 4;
    for (int i = threadIdx.x; i < 4 * 512; i += blockDim.x)
        xs[i / 512][i % 512] = X[(long)b0 * 512 + i];
    __syncthreads();
    int o = threadIdx.x;
    if (o >= 100) return;
    float acc0 = 0.f, acc1 = 0.f, acc2 = 0.f, acc3 = 0.f;
    for (int k = 0; k < 512; k++) {
        float w = WT[k * 100 + o];
        acc0 = fmaf(xs[0][k], w, acc0);
        acc1 = fmaf(xs[1][k], w, acc1);
        acc2 = fmaf(xs[2][k], w, acc2);
        acc3 = fmaf(xs[3][k], w, acc3);
    }
    float bb = bias[o];
    out[(b0 + 0) * 100 + o] = acc0 + bb;
    out[(b0 + 1) * 100 + o] = acc1 + bb;
    out[(b0 + 2) * 100 + o] = acc2 + bb;
    out[(b0 + 3) * 100 + o] = acc3 + bb;
}

// ---------------- launch ----------------------------------------------------
extern "C" void kernel_launch(void* const* d_in, const int* in_sizes, int n_in,
                              void* d_out, int out_size) {
    const float* x     = (const float*)d_in[0];
    const float* c1_bw = (const float*)d_in[1];
    const float* c1_sw = (const float*)d_in[2];
    const float* c1_sc = (const float*)d_in[3];
    const float* c2_bw = (const float*)d_in[4];
    const float* c2_sw = (const float*)d_in[5];
    const float* c2_sc = (const float*)d_in[6];
    const float* c3_bw = (const float*)d_in[7];
    const float* c3_sw = (const float*)d_in[8];
    const float* c3_sc = (const float*)d_in[9];
    const float* lin_w = (const float*)d_in[10];
    const float* lin_b = (const float*)d_in[11];
    float* out = (float*)d_out;

    float *p_bas1, *p_bas2, *p_bas3, *p_pool3;
    float *p_sw1, *p_sw2, *p_sw3, *p_wt;
    cudaGetSymbolAddress((void**)&p_bas1,  d_bas1);
    cudaGetSymbolAddress((void**)&p_bas2,  d_bas2);
    cudaGetSymbolAddress((void**)&p_bas3,  d_bas3);
    cudaGetSymbolAddress((void**)&p_pool3, d_pool3);
    cudaGetSymbolAddress((void**)&p_sw1,   d_sw1);
    cudaGetSymbolAddress((void**)&p_sw2,   d_sw2);
    cudaGetSymbolAddress((void**)&p_sw3,   d_sw3);
    cudaGetSymbolAddress((void**)&p_wt,    d_wt);

    // prep: weights + SoA halos
    {
        int total = 8*27*7 + 16*72*7 + 32*144*7 + 100*512
                  + BATCH*8*(4*18-4) + BATCH*16*(4*10-4);
        prep_all_kernel<<<(total + 255) / 256, 256>>>(
            c1_bw, c1_sw, c1_sc, c2_bw, c2_sw, c2_sc, c3_bw, c3_sw, c3_sc,
            lin_w, p_sw1, p_sw2, p_sw3, p_wt, p_bas2, p_bas3);
    }
    // layer-1 input basis
    {
        int n = BATCH * 3 * 34 * 34;
        basis_in_kernel<<<(n + 255) / 256, 256>>>(x, p_bas1);
    }
    // L1: smem-staged, half image per block, all 8 channels
    convpool1_kernel<<<BATCH * 2, 128>>>(p_bas1, p_sw1, p_bas2);
    // L2: smem-staged, half image per block, all 16 channels
    convpool2_kernel<<<BATCH * 2, 128>>>(p_bas2, p_sw2, p_bas3);
    // L3: smem-staged, half image per block, all 32 channels
    convpool3_kernel<<<BATCH * 2, 64>>>(p_bas3, p_sw3, p_pool3);
    // linear
    linear_kernel<<<BATCH / 4, 128>>>(p_pool3, p_wt, lin_b, out);
}

// round 13
// speedup vs baseline: 1.0098x; 1.0098x over previous
#include <cuda_runtime.h>
#include <cuda_bf16.h>

#define BATCH 256

// zero-value basis constants: v=0 -> t=4.5, i0=4, u=0.5
#define ZB2 (1.f/48.f)
#define ZB3 (23.f/48.f)

typedef unsigned long long u64;

// ---------------- packed f32x2 helpers (Blackwell FFMA2) -------------------
__device__ __forceinline__ u64 pack_dup(float x) {
    u64 r; asm("mov.b64 %0, {%1, %1};" : "=l"(r) : "f"(x)); return r;
}
__device__ __forceinline__ void unpack2(u64 v, float& x, float& y) {
    asm("mov.b64 {%0, %1}, %2;" : "=f"(x), "=f"(y) : "l"(v));
}
__device__ __forceinline__ void ffma2(u64& d, u64 a, u64 b) {
    asm("fma.rn.f32x2 %0, %1, %2, %0;" : "+l"(d) : "l"(a), "l"(b));
}

// ---------------- scratch (static device globals) ---------------------------
// SoA basis: [B][C][7 slots][P rows][RP padded cols]
__device__ float d_bas1 [BATCH * 3  * 7 * 34 * 36];
__device__ float d_bas2 [BATCH * 8  * 7 * 18 * 20];
__device__ float d_bas3 [BATCH * 16 * 7 * 10 * 12];
__device__ float d_pool3[BATCH * 32 * 4 * 4];
// weights: L1 [27][7][8]; L2 [4 tiles][72][7][4]; L3 [8 tiles][144][7][4]
__device__ float d_sw1[27 * 7 * 8];
__device__ float d_sw2[4 * 72 * 7 * 4];
__device__ float d_sw3[8 * 144 * 7 * 4];
__device__ float d_wt [512 * 100];   // transposed lin_w: [k][o]

// ---------------- basis evaluation (7 slots) --------------------------------
__device__ __forceinline__ void basis7(float v, float* sv) {
    sv[0] = v * (1.f / (1.f + __expf(-v)));          // silu
    float t  = (v + 3.f) * 1.5f;
    bool valid = (t >= 0.f) && (t < 9.f);
    float fi = floorf(t);
    int   i0 = (int)fi;
    float u  = t - fi;
    float u2 = u * u, u3 = u2 * u;
    float q3 = u3 * (1.f / 6.f);
    float q2 = ((3.f * u2 - 3.f * u3) + 3.f * u + 1.f) * (1.f / 6.f);
    float q1 = (3.f * u3 - 6.f * u2 + 4.f) * (1.f / 6.f);
    float iu = 1.f - u;
    float q0 = iu * iu * iu * (1.f / 6.f);
    if (!valid) { q0 = q1 = q2 = q3 = 0.f; i0 = -1000; }
#pragma unroll
    for (int m = 0; m < 6; m++) {
        int d = i0 - m;
        sv[1 + m] = (d == 0) ? q3 : (d == 1) ? q2 : (d == 2) ? q1
                  : (d == 3) ? q0 : 0.f;
    }
}

// ---------------- layer-1 input basis (SoA) ---------------------------------
__global__ void basis_in_kernel(const float* __restrict__ X, float* __restrict__ BAS) {
    constexpr int P = 34, RP = 36, HW = 32;
    int idx = blockIdx.x * blockDim.x + threadIdx.x;
    if (idx >= BATCH * 3 * P * P) return;
    int xp = idx % P;
    int yp = (idx / P) % P;
    int bc = idx / (P * P);
    float sv[7];
    if (xp == 0 || xp == P - 1 || yp == 0 || yp == P - 1) {
        sv[0] = 0.f; sv[1] = 0.f; sv[2] = ZB2; sv[3] = ZB3;
        sv[4] = ZB3; sv[5] = ZB2; sv[6] = 0.f;
    } else {
        float v = X[((long)bc * HW + (yp - 1)) * HW + (xp - 1)];
        basis7(v, sv);
    }
    float* base = BAS + ((long)bc * 7 * P + yp) * RP + xp;
#pragma unroll
    for (int s = 0; s < 7; s++) base[(long)s * P * RP] = sv[s];
}

// -------- fused conv3x3 + pool + next-basis, POS=2, global SoA reads --------
// thread = 2 adjacent x positions (x0 = 2k), one row y, TILE output channels.
// Warp lanes cover consecutive x-groups of the SAME row(s) -> coalesced
// LDG.64 pairs (~128B/row). Weights broadcast from smem. Pool via shfl.
template<int C, int HW, int RPI, int TILE, int NTILE, int PO, int RPO, bool WB>
__global__ void __launch_bounds__(256)
convpool_soa2(const float* __restrict__ BAS,   // [B][C][7][P][RPI]
              const float* __restrict__ SW,    // [NTILE][C*9][7][TILE]
              float* __restrict__ OUT) {
    constexpr int F   = C * 9;
    constexpr int P   = HW + 2;
    constexpr int HX2 = HW / 2;
    constexpr int OC  = NTILE * TILE;
    constexpr int NP  = TILE / 2;
    __shared__ __align__(16) float sw[F * 7 * TILE];

    const float* gsw = SW + blockIdx.y * (F * 7 * TILE);
    for (int i = threadIdx.x; i < F * 7 * TILE / 4; i += 256)
        reinterpret_cast<float4*>(sw)[i] = reinterpret_cast<const float4*>(gsw)[i];
    __syncthreads();

    int p  = blockIdx.x * 256 + threadIdx.x;
    int k  = p % HX2;
    int y  = (p / HX2) % HW;
    int b  = p / (HX2 * HW);
    int x0 = 2 * k;

    u64 acc2[2][NP];
#pragma unroll
    for (int pos = 0; pos < 2; pos++)
#pragma unroll
        for (int q = 0; q < NP; q++) acc2[pos][q] = 0ull;

    for (int c = 0; c < C; c++) {
        const float* Bc = BAS + (long)(b * C + c) * 7 * P * RPI;
#pragma unroll
        for (int ky = 0; ky < 3; ky++) {
            float bv[7][4];
#pragma unroll
            for (int s = 0; s < 7; s++) {
                const float* q = Bc + ((long)s * P + (y + ky)) * RPI + x0;
                float2 a = *reinterpret_cast<const float2*>(q);
                float2 e = *reinterpret_cast<const float2*>(q + 2);
                bv[s][0] = a.x; bv[s][1] = a.y; bv[s][2] = e.x; bv[s][3] = e.y;
            }
            const float* wbase = sw + (c * 9 + ky * 3) * 7 * TILE;
#pragma unroll
            for (int kx = 0; kx < 3; kx++) {
#pragma unroll
                for (int s = 0; s < 7; s++) {
                    const float* wp = wbase + (kx * 7 + s) * TILE;
                    ulonglong2 wA = *reinterpret_cast<const ulonglong2*>(wp);
                    ulonglong2 wB;
                    if (TILE == 8) wB = *reinterpret_cast<const ulonglong2*>(wp + 4);
#pragma unroll
                    for (int pos = 0; pos < 2; pos++) {
                        u64 sp = pack_dup(bv[s][kx + pos]);
                        ffma2(acc2[pos][0], sp, wA.x);
                        if (NP > 1) ffma2(acc2[pos][1], sp, wA.y);
                        if (TILE == 8) {
                            ffma2(acc2[pos][2], sp, wB.x);
                            ffma2(acc2[pos][3], sp, wB.y);
                        }
                    }
                }
            }
        }
    }

    // horizontal pool (the thread's 2 x), vertical via shfl partner row y^1
    float hm[TILE];
#pragma unroll
    for (int q = 0; q < NP; q++) {
        float a0, a1, b0, b1;
        unpack2(acc2[0][q], a0, a1);
        unpack2(acc2[1][q], b0, b1);
        hm[2 * q]     = fmaxf(a0, b0);
        hm[2 * q + 1] = fmaxf(a1, b1);
    }
#pragma unroll
    for (int j = 0; j < TILE; j++) {
        float o = __shfl_xor_sync(0xffffffffu, hm[j], HX2);
        hm[j] = fmaxf(hm[j], o);
    }

    if ((y & 1) == 0) {
        int yo = y >> 1;
        int xo = k;
        if (WB) {
#pragma unroll
            for (int j = 0; j < TILE; j++) {
                float sv[7];
                basis7(hm[j], sv);
                int ch = blockIdx.y * TILE + j;
                float* base = OUT + (((long)(b * OC + ch) * 7) * PO + (yo + 1)) * RPO
                                  + (xo + 1);
#pragma unroll
                for (int s = 0; s < 7; s++) base[(long)s * PO * RPO] = sv[s];
            }
        } else {
#pragma unroll
            for (int j = 0; j < TILE; j++) {
                int ch = blockIdx.y * TILE + j;
                OUT[(((long)b * OC + ch) * (HW / 2) + yo) * (HW / 2) + xo] = hm[j];
            }
        }
    }
}

// ---------------- merged weight prep + SoA halo fill ------------------------
__device__ __forceinline__ float sw_val(const float* bw, const float* sp,
                                        const float* sc, int o, int f, int slot, int F) {
    if (slot == 0) return bw[o * F + f];
    return sp[(o * F + f) * 6 + (slot - 1)] * sc[o * F + f];
}

__device__ __forceinline__ void halo_fill(float* bas, int i, int P, int RP) {
    int hc  = 4 * P - 4;
    int img = i / hc;
    int kk  = i % hc;
    int xp, yp;
    if (kk < P)          { yp = 0;      xp = kk; }
    else if (kk < 2 * P) { yp = P - 1;  xp = kk - P; }
    else {
        int rr = kk - 2 * P;
        yp = 1 + (rr >> 1);
        xp = (rr & 1) ? (P - 1) : 0;
    }
    const float zb[7] = {0.f, 0.f, ZB2, ZB3, ZB3, ZB2, 0.f};
    float* base = bas + ((long)img * 7 * P + yp) * RP + xp;
#pragma unroll
    for (int s = 0; s < 7; s++) base[(long)s * P * RP] = zb[s];
}

__global__ void prep_all_kernel(const float* __restrict__ c1_bw, const float* __restrict__ c1_sw,
                                const float* __restrict__ c1_sc,
                                const float* __restrict__ c2_bw, const float* __restrict__ c2_sw,
                                const float* __restrict__ c2_sc,
                                const float* __restrict__ c3_bw, const float* __restrict__ c3_sw,
                                const float* __restrict__ c3_sc,
                                const float* __restrict__ lin_w,
                                float* __restrict__ sw1, float* __restrict__ sw2,
                                float* __restrict__ sw3, float* __restrict__ wt,
                                float* __restrict__ bas2, float* __restrict__ bas3) {
    const int N1 = 8 * 27 * 7, N2 = 16 * 72 * 7, N3 = 32 * 144 * 7, NW = 100 * 512;
    const int H2 = BATCH * 8 * (4 * 18 - 4);
    const int H3 = BATCH * 16 * (4 * 10 - 4);
    int idx = blockIdx.x * blockDim.x + threadIdx.x;
    int e1 = N1, e2 = e1 + N2, e3 = e2 + N3, e4 = e3 + NW, e5 = e4 + H2, e6 = e5 + H3;
    if (idx < e1) {
        int slot = idx % 7, f = (idx / 7) % 27, o = idx / (7 * 27);
        sw1[(f * 7 + slot) * 8 + o] = sw_val(c1_bw, c1_sw, c1_sc, o, f, slot, 27);
    } else if (idx < e2) {
        int i = idx - e1;
        int slot = i % 7, f = (i / 7) % 72, o = i / (7 * 72);
        sw2[(((o >> 2) * 72 + f) * 7 + slot) * 4 + (o & 3)] =
            sw_val(c2_bw, c2_sw, c2_sc, o, f, slot, 72);
    } else if (idx < e3) {
        int i = idx - e2;
        int slot = i % 7, f = (i / 7) % 144, o = i / (7 * 144);
        sw3[(((o >> 2) * 144 + f) * 7 + slot) * 4 + (o & 3)] =
            sw_val(c3_bw, c3_sw, c3_sc, o, f, slot, 144);
    } else if (idx < e4) {
        int i = idx - e3;
        int o = i / 512, k = i % 512;
        wt[k * 100 + o] = lin_w[i];
    } else if (idx < e5) halo_fill(bas2, idx - e4, 18, 20);
    else if (idx < e6)   halo_fill(bas3, idx - e5, 10, 12);
}

// ---------------- final linear: [256,512] @ [512,100]^T + b -----------------
__global__ void __launch_bounds__(128)
linear_kernel(const float* __restrict__ X, const float* __restrict__ WT,
              const float* __restrict__ bias, float* __restrict__ out) {
    __shared__ float xs[4][512];
    int b0 = blockIdx.x * 4;
    for (int i = threadIdx.x; i < 4 * 512; i += blockDim.x)
        xs[i / 512][i % 512] = X[(long)b0 * 512 + i];
    __syncthreads();
    int o = threadIdx.x;
    if (o >= 100) return;
    float acc0 = 0.f, acc1 = 0.f, acc2 = 0.f, acc3 = 0.f;
    for (int k = 0; k < 512; k++) {
        float w = WT[k * 100 + o];
        acc0 = fmaf(xs[0][k], w, acc0);
        acc1 = fmaf(xs[1][k], w, acc1);
        acc2 = fmaf(xs[2][k], w, acc2);
        acc3 = fmaf(xs[3][k], w, acc3);
    }
    float bb = bias[o];
    out[(b0 + 0) * 100 + o] = acc0 + bb;
    out[(b0 + 1) * 100 + o] = acc1 + bb;
    out[(b0 + 2) * 100 + o] = acc2 + bb;
    out[(b0 + 3) * 100 + o] = acc3 + bb;
}

// ---------------- launch ----------------------------------------------------
extern "C" void kernel_launch(void* const* d_in, const int* in_sizes, int n_in,
                              void* d_out, int out_size) {
    const float* x     = (const float*)d_in[0];
    const float* c1_bw = (const float*)d_in[1];
    const float* c1_sw = (const float*)d_in[2];
    const float* c1_sc = (const float*)d_in[3];
    const float* c2_bw = (const float*)d_in[4];
    const float* c2_sw = (const float*)d_in[5];
    const float* c2_sc = (const float*)d_in[6];
    const float* c3_bw = (const float*)d_in[7];
    const float* c3_sw = (const float*)d_in[8];
    const float* c3_sc = (const float*)d_in[9];
    const float* lin_w = (const float*)d_in[10];
    const float* lin_b = (const float*)d_in[11];
    float* out = (float*)d_out;

    float *p_bas1, *p_bas2, *p_bas3, *p_pool3;
    float *p_sw1, *p_sw2, *p_sw3, *p_wt;
    cudaGetSymbolAddress((void**)&p_bas1,  d_bas1);
    cudaGetSymbolAddress((void**)&p_bas2,  d_bas2);
    cudaGetSymbolAddress((void**)&p_bas3,  d_bas3);
    cudaGetSymbolAddress((void**)&p_pool3, d_pool3);
    cudaGetSymbolAddress((void**)&p_sw1,   d_sw1);
    cudaGetSymbolAddress((void**)&p_sw2,   d_sw2);
    cudaGetSymbolAddress((void**)&p_sw3,   d_sw3);
    cudaGetSymbolAddress((void**)&p_wt,    d_wt);

    // prep: weights + SoA halos
    {
        int total = 8*27*7 + 16*72*7 + 32*144*7 + 100*512
                  + BATCH*8*(4*18-4) + BATCH*16*(4*10-4);
        prep_all_kernel<<<(total + 255) / 256, 256>>>(
            c1_bw, c1_sw, c1_sc, c2_bw, c2_sw, c2_sc, c3_bw, c3_sw, c3_sc,
            lin_w, p_sw1, p_sw2, p_sw3, p_wt, p_bas2, p_bas3);
    }
    // layer-1 input basis
    {
        int n = BATCH * 3 * 34 * 34;
        basis_in_kernel<<<(n + 255) / 256, 256>>>(x, p_bas1);
    }
    // L1: C=3 HW=32 POS=2 TILE=8 NTILE=1 -> bas2 (18,20). 512 blocks.
    {
        dim3 g(BATCH * 32 * 16 / 256, 1);
        convpool_soa2<3, 32, 36, 8, 1, 18, 20, true><<<g, 256>>>(p_bas1, p_sw1, p_bas2);
    }
    // L2: C=8 HW=16 POS=2 TILE=4 NTILE=4 -> bas3 (10,12). 512 blocks.
    {
        dim3 g(BATCH * 16 * 8 / 256, 4);
        convpool_soa2<8, 16, 20, 4, 4, 10, 12, true><<<g, 256>>>(p_bas2, p_sw2, p_bas3);
    }
    // L3: C=16 HW=8 POS=2 TILE=4 NTILE=8 -> pool3. 256 blocks.
    {
        dim3 g(BATCH * 8 * 4 / 256, 8);
        convpool_soa2<16, 8, 12, 4, 8, 4, 4, false><<<g, 256>>>(p_bas3, p_sw3, p_pool3);
    }
    // linear
    linear_kernel<<<BATCH / 4, 128>>>(p_pool3, p_wt, lin_b, out);
}

// round 16
// speedup vs baseline: 1.0933x; 1.0827x over previous
#include <cuda_runtime.h>
#include <cuda_bf16.h>

#define BATCH 256

// zero-value basis constants: v=0 -> t=4.5, i0=4, u=0.5
#define ZB2 (1.f/48.f)
#define ZB3 (23.f/48.f)

typedef unsigned long long u64;

// ---------------- packed f32x2 helpers (Blackwell FFMA2) -------------------
__device__ __forceinline__ u64 pack_dup(float x) {
    u64 r; asm("mov.b64 %0, {%1, %1};" : "=l"(r) : "f"(x)); return r;
}
__device__ __forceinline__ void unpack2(u64 v, float& x, float& y) {
    asm("mov.b64 {%0, %1}, %2;" : "=f"(x), "=f"(y) : "l"(v));
}
__device__ __forceinline__ void ffma2(u64& d, u64 a, u64 b) {
    asm("fma.rn.f32x2 %0, %1, %2, %0;" : "+l"(d) : "l"(a), "l"(b));
}

// ---------------- scratch (static device globals) ---------------------------
// SoA basis: [B][C][7 slots][P rows][RP padded cols]
__device__ float d_bas1 [BATCH * 3  * 7 * 34 * 36];
__device__ float d_bas2 [BATCH * 8  * 7 * 18 * 20];
__device__ float d_bas3 [BATCH * 16 * 7 * 10 * 12];
__device__ float d_pool3[BATCH * 32 * 4 * 4];
// weights: [NTILE][F][7][8]
__device__ float d_sw1[1 * 27  * 7 * 8];
__device__ float d_sw2[2 * 72  * 7 * 8];
__device__ float d_sw3[4 * 144 * 7 * 8];
__device__ float d_wt [512 * 100];   // transposed lin_w: [k][o]

// ---------------- basis evaluation (7 slots) --------------------------------
__device__ __forceinline__ void basis7(float v, float* sv) {
    sv[0] = v * (1.f / (1.f + __expf(-v)));          // silu
    float t  = (v + 3.f) * 1.5f;
    bool valid = (t >= 0.f) && (t < 9.f);
    float fi = floorf(t);
    int   i0 = (int)fi;
    float u  = t - fi;
    float u2 = u * u, u3 = u2 * u;
    float q3 = u3 * (1.f / 6.f);
    float q2 = ((3.f * u2 - 3.f * u3) + 3.f * u + 1.f) * (1.f / 6.f);
    float q1 = (3.f * u3 - 6.f * u2 + 4.f) * (1.f / 6.f);
    float iu = 1.f - u;
    float q0 = iu * iu * iu * (1.f / 6.f);
    if (!valid) { q0 = q1 = q2 = q3 = 0.f; i0 = -1000; }
#pragma unroll
    for (int m = 0; m < 6; m++) {
        int d = i0 - m;
        sv[1 + m] = (d == 0) ? q3 : (d == 1) ? q2 : (d == 2) ? q1
                  : (d == 3) ? q0 : 0.f;
    }
}

// ---------------- layer-1 input basis (SoA) ---------------------------------
__global__ void basis_in_kernel(const float* __restrict__ X, float* __restrict__ BAS) {
    constexpr int P = 34, RP = 36, HW = 32;
    int idx = blockIdx.x * blockDim.x + threadIdx.x;
    if (idx >= BATCH * 3 * P * P) return;
    int xp = idx % P;
    int yp = (idx / P) % P;
    int bc = idx / (P * P);
    float sv[7];
    if (xp == 0 || xp == P - 1 || yp == 0 || yp == P - 1) {
        sv[0] = 0.f; sv[1] = 0.f; sv[2] = ZB2; sv[3] = ZB3;
        sv[4] = ZB3; sv[5] = ZB2; sv[6] = 0.f;
    } else {
        float v = X[((long)bc * HW + (yp - 1)) * HW + (xp - 1)];
        basis7(v, sv);
    }
    float* base = BAS + ((long)bc * 7 * P + yp) * RP + xp;
#pragma unroll
    for (int s = 0; s < 7; s++) base[(long)s * P * RP] = sv[s];
}

// -------- fused conv3x3 + pool + next-basis; TILE=8, POS in {2,4} -----------
// thread = POS adjacent x positions (x0 = POS*k), one row y, 8 out channels.
// Warp lanes cover consecutive x-groups of the same rows -> coalesced loads.
// Weights broadcast from smem. Pool via shfl (partner row y^1 = lane^HX).
template<int C, int HW, int RPI, int POS, int NTILE, int PO, int RPO, bool WB, int BLK>
__global__ void __launch_bounds__(BLK)
convpool_t8(const float* __restrict__ BAS,   // [B][C][7][P][RPI]
            const float* __restrict__ SW,    // [NTILE][C*9][7][8]
            float* __restrict__ OUT) {
    constexpr int F   = C * 9;
    constexpr int P   = HW + 2;
    constexpr int HX  = HW / POS;
    constexpr int OC  = NTILE * 8;
    constexpr int XL  = POS / 2;
    __shared__ __align__(16) float sw[F * 7 * 8];

    const float* gsw = SW + blockIdx.y * (F * 7 * 8);
    for (int i = threadIdx.x; i < F * 7 * 8 / 4; i += BLK)
        reinterpret_cast<float4*>(sw)[i] = reinterpret_cast<const float4*>(gsw)[i];
    __syncthreads();

    int p  = blockIdx.x * BLK + threadIdx.x;
    int k  = p % HX;
    int y  = (p / HX) % HW;
    int b  = p / (HX * HW);
    int x0 = POS * k;

    u64 acc2[POS][4];
#pragma unroll
    for (int pos = 0; pos < POS; pos++)
#pragma unroll
        for (int q = 0; q < 4; q++) acc2[pos][q] = 0ull;

    for (int c = 0; c < C; c++) {
        const float* Bc = BAS + (long)(b * C + c) * 7 * P * RPI;
#pragma unroll
        for (int ky = 0; ky < 3; ky++) {
            float bv[7][POS + 2];
#pragma unroll
            for (int s = 0; s < 7; s++) {
                const float* q = Bc + ((long)s * P + (y + ky)) * RPI + x0;
                if (POS == 4) {
                    float4 a = *reinterpret_cast<const float4*>(q);
                    float2 e = *reinterpret_cast<const float2*>(q + 4);
                    bv[s][0] = a.x; bv[s][1] = a.y; bv[s][2] = a.z;
                    bv[s][3] = a.w; bv[s][4] = e.x; bv[s][5] = e.y;
                } else {
                    float2 a = *reinterpret_cast<const float2*>(q);
                    float2 e = *reinterpret_cast<const float2*>(q + 2);
                    bv[s][0] = a.x; bv[s][1] = a.y; bv[s][2] = e.x; bv[s][3] = e.y;
                }
            }
            const float* wbase = sw + (c * 9 + ky * 3) * 7 * 8;
#pragma unroll
            for (int kx = 0; kx < 3; kx++) {
#pragma unroll
                for (int s = 0; s < 7; s++) {
                    const float* wp = wbase + (kx * 7 + s) * 8;
                    ulonglong2 wA = *reinterpret_cast<const ulonglong2*>(wp);
                    ulonglong2 wB = *reinterpret_cast<const ulonglong2*>(wp + 4);
#pragma unroll
                    for (int pos = 0; pos < POS; pos++) {
                        u64 sp = pack_dup(bv[s][kx + pos]);
                        ffma2(acc2[pos][0], sp, wA.x);
                        ffma2(acc2[pos][1], sp, wA.y);
                        ffma2(acc2[pos][2], sp, wB.x);
                        ffma2(acc2[pos][3], sp, wB.y);
                    }
                }
            }
        }
    }

    // horizontal pool within thread, vertical via shfl partner row y^1
    float hm[XL][8];
#pragma unroll
    for (int q = 0; q < 4; q++)
#pragma unroll
        for (int xl = 0; xl < XL; xl++) {
            float a0, a1, b0, b1;
            unpack2(acc2[2 * xl][q],     a0, a1);
            unpack2(acc2[2 * xl + 1][q], b0, b1);
            hm[xl][2 * q]     = fmaxf(a0, b0);
            hm[xl][2 * q + 1] = fmaxf(a1, b1);
        }
#pragma unroll
    for (int xl = 0; xl < XL; xl++)
#pragma unroll
        for (int j = 0; j < 8; j++) {
            float o = __shfl_xor_sync(0xffffffffu, hm[xl][j], HX);
            hm[xl][j] = fmaxf(hm[xl][j], o);
        }

    if ((y & 1) == 0) {
        int yo = y >> 1;
        if (WB) {
#pragma unroll
            for (int j = 0; j < 8; j++)
#pragma unroll
                for (int xl = 0; xl < XL; xl++) {
                    float sv[7];
                    basis7(hm[xl][j], sv);
                    int ch = blockIdx.y * 8 + j;
                    int xo = XL * k + xl;
                    float* base = OUT + (((long)(b * OC + ch) * 7) * PO + (yo + 1)) * RPO
                                      + (xo + 1);
#pragma unroll
                    for (int s = 0; s < 7; s++) base[(long)s * PO * RPO] = sv[s];
                }
        } else {
#pragma unroll
            for (int j = 0; j < 8; j++)
#pragma unroll
                for (int xl = 0; xl < XL; xl++) {
                    int ch = blockIdx.y * 8 + j;
                    int xo = XL * k + xl;
                    OUT[(((long)b * OC + ch) * (HW / 2) + yo) * (HW / 2) + xo] = hm[xl][j];
                }
        }
    }
}

// ---------------- merged weight prep + SoA halo fill ------------------------
__device__ __forceinline__ float sw_val(const float* bw, const float* sp,
                                        const float* sc, int o, int f, int slot, int F) {
    if (slot == 0) return bw[o * F + f];
    return sp[(o * F + f) * 6 + (slot - 1)] * sc[o * F + f];
}

__device__ __forceinline__ void halo_fill(float* bas, int i, int P, int RP) {
    int hc  = 4 * P - 4;
    int img = i / hc;
    int kk  = i % hc;
    int xp, yp;
    if (kk < P)          { yp = 0;      xp = kk; }
    else if (kk < 2 * P) { yp = P - 1;  xp = kk - P; }
    else {
        int rr = kk - 2 * P;
        yp = 1 + (rr >> 1);
        xp = (rr & 1) ? (P - 1) : 0;
    }
    const float zb[7] = {0.f, 0.f, ZB2, ZB3, ZB3, ZB2, 0.f};
    float* base = bas + ((long)img * 7 * P + yp) * RP + xp;
#pragma unroll
    for (int s = 0; s < 7; s++) base[(long)s * P * RP] = zb[s];
}

__global__ void prep_all_kernel(const float* __restrict__ c1_bw, const float* __restrict__ c1_sw,
                                const float* __restrict__ c1_sc,
                                const float* __restrict__ c2_bw, const float* __restrict__ c2_sw,
                                const float* __restrict__ c2_sc,
                                const float* __restrict__ c3_bw, const float* __restrict__ c3_sw,
                                const float* __restrict__ c3_sc,
                                const float* __restrict__ lin_w,
                                float* __restrict__ sw1, float* __restrict__ sw2,
                                float* __restrict__ sw3, float* __restrict__ wt,
                                float* __restrict__ bas2, float* __restrict__ bas3) {
    const int N1 = 8 * 27 * 7, N2 = 16 * 72 * 7, N3 = 32 * 144 * 7, NW = 100 * 512;
    const int H2 = BATCH * 8 * (4 * 18 - 4);
    const int H3 = BATCH * 16 * (4 * 10 - 4);
    int idx = blockIdx.x * blockDim.x + threadIdx.x;
    int e1 = N1, e2 = e1 + N2, e3 = e2 + N3, e4 = e3 + NW, e5 = e4 + H2, e6 = e5 + H3;
    if (idx < e1) {
        int slot = idx % 7, f = (idx / 7) % 27, o = idx / (7 * 27);
        sw1[(f * 7 + slot) * 8 + o] = sw_val(c1_bw, c1_sw, c1_sc, o, f, slot, 27);
    } else if (idx < e2) {
        int i = idx - e1;
        int slot = i % 7, f = (i / 7) % 72, o = i / (7 * 72);
        sw2[(((o >> 3) * 72 + f) * 7 + slot) * 8 + (o & 7)] =
            sw_val(c2_bw, c2_sw, c2_sc, o, f, slot, 72);
    } else if (idx < e3) {
        int i = idx - e2;
        int slot = i % 7, f = (i / 7) % 144, o = i / (7 * 144);
        sw3[(((o >> 3) * 144 + f) * 7 + slot) * 8 + (o & 7)] =
            sw_val(c3_bw, c3_sw, c3_sc, o, f, slot, 144);
    } else if (idx < e4) {
        int i = idx - e3;
        int o = i / 512, k = i % 512;
        wt[k * 100 + o] = lin_w[i];
    } else if (idx < e5) halo_fill(bas2, idx - e4, 18, 20);
    else if (idx < e6)   halo_fill(bas3, idx - e5, 10, 12);
}

// ---------------- final linear: [256,512] @ [512,100]^T + b -----------------
__global__ void __launch_bounds__(128)
linear_kernel(const float* __restrict__ X, const float* __restrict__ WT,
              const float* __restrict__ bias, float* __restrict__ out) {
    __shared__ float xs[4][512];
    int b0 = blockIdx.x * 4;
    for (int i = threadIdx.x; i < 4 * 512; i += blockDim.x)
        xs[i / 512][i % 512] = X[(long)b0 * 512 + i];
    __syncthreads();
    int o = threadIdx.x;
    if (o >= 100) return;
    float acc0 = 0.f, acc1 = 0.f, acc2 = 0.f, acc3 = 0.f;
    for (int k = 0; k < 512; k++) {
        float w = WT[k * 100 + o];
        acc0 = fmaf(xs[0][k], w, acc0);
        acc1 = fmaf(xs[1][k], w, acc1);
        acc2 = fmaf(xs[2][k], w, acc2);
        acc3 = fmaf(xs[3][k], w, acc3);
    }
    float bb = bias[o];
    out[(b0 + 0) * 100 + o] = acc0 + bb;
    out[(b0 + 1) * 100 + o] = acc1 + bb;
    out[(b0 + 2) * 100 + o] = acc2 + bb;
    out[(b0 + 3) * 100 + o] = acc3 + bb;
}

// ---------------- launch ----------------------------------------------------
extern "C" void kernel_launch(void* const* d_in, const int* in_sizes, int n_in,
                              void* d_out, int out_size) {
    const float* x     = (const float*)d_in[0];
    const float* c1_bw = (const float*)d_in[1];
    const float* c1_sw = (const float*)d_in[2];
    const float* c1_sc = (const float*)d_in[3];
    const float* c2_bw = (const float*)d_in[4];
    const float* c2_sw = (const float*)d_in[5];
    const float* c2_sc = (const float*)d_in[6];
    const float* c3_bw = (const float*)d_in[7];
    const float* c3_sw = (const float*)d_in[8];
    const float* c3_sc = (const float*)d_in[9];
    const float* lin_w = (const float*)d_in[10];
    const float* lin_b = (const float*)d_in[11];
    float* out = (float*)d_out;

    float *p_bas1, *p_bas2, *p_bas3, *p_pool3;
    float *p_sw1, *p_sw2, *p_sw3, *p_wt;
    cudaGetSymbolAddress((void**)&p_bas1,  d_bas1);
    cudaGetSymbolAddress((void**)&p_bas2,  d_bas2);
    cudaGetSymbolAddress((void**)&p_bas3,  d_bas3);
    cudaGetSymbolAddress((void**)&p_pool3, d_pool3);
    cudaGetSymbolAddress((void**)&p_sw1,   d_sw1);
    cudaGetSymbolAddress((void**)&p_sw2,   d_sw2);
    cudaGetSymbolAddress((void**)&p_sw3,   d_sw3);
    cudaGetSymbolAddress((void**)&p_wt,    d_wt);

    // prep: weights + SoA halos
    {
        int total = 8*27*7 + 16*72*7 + 32*144*7 + 100*512
                  + BATCH*8*(4*18-4) + BATCH*16*(4*10-4);
        prep_all_kernel<<<(total + 255) / 256, 256>>>(
            c1_bw, c1_sw, c1_sc, c2_bw, c2_sw, c2_sc, c3_bw, c3_sw, c3_sc,
            lin_w, p_sw1, p_sw2, p_sw3, p_wt, p_bas2, p_bas3);
    }
    // layer-1 input basis
    {
        int n = BATCH * 3 * 34 * 34;
        basis_in_kernel<<<(n + 255) / 256, 256>>>(x, p_bas1);
    }
    // L1: C=3 HW=32 POS=4 TILE=8 NTILE=1 -> bas2 (18,20). 256 blocks x 256.
    {
        dim3 g(BATCH * 32 * 8 / 256, 1);
        convpool_t8<3, 32, 36, 4, 1, 18, 20, true, 256><<<g, 256>>>(p_bas1, p_sw1, p_bas2);
    }
    // L2: C=8 HW=16 POS=4 TILE=8 NTILE=2 -> bas3 (10,12). 256 blocks x 128.
    {
        dim3 g(BATCH * 16 * 4 / 128, 2);
        convpool_t8<8, 16, 20, 4, 2, 10, 12, true, 128><<<g, 128>>>(p_bas2, p_sw2, p_bas3);
    }
    // L3: C=16 HW=8 POS=2 TILE=8 NTILE=4 -> pool3. 256 blocks x 128.
    {
        dim3 g(BATCH * 8 * 4 / 128, 4);
        convpool_t8<16, 8, 12, 2, 4, 4, 4, false, 128><<<g, 128>>>(p_bas3, p_sw3, p_pool3);
    }
    // linear
    linear_kernel<<<BATCH / 4, 128>>>(p_pool3, p_wt, lin_b, out);
}